// round 14
// baseline (speedup 1.0000x reference)
#include <cuda_runtime.h>
#include <cuda_fp16.h>
#include <mma.h>

using namespace nvcuda;

#define BB   64
#define TT   512
#define KK   512
#define G3   1536
#define LDB  520
#define NTHREADS 384
#define SLD  20
#define TILE_F (16*SLD)
#define ABUF_LD 24

__device__ __half g_h_hi[2][2][BB * KK];
__device__ __half g_h_lo[2][2][BB * KK];
__device__ float  g_gi0[(size_t)TT * BB * G3];
__device__ __align__(128) unsigned int g_c0g[2][32];
__device__ __align__(128) unsigned int g_c1g[2][32];

__device__ __forceinline__ void load_weights(const float* __restrict__ W,
                                             __half* shi, __half* slo, int cidx) {
    for (int idx = threadIdx.x; idx < 48 * KK; idx += NTHREADS) {
        int row = idx >> 9, k = idx & 511;
        int grow = (row >> 4) * 512 + cidx * 16 + (row & 15);
        float v = W[(size_t)grow * KK + k];
        __half h = __float2half_rn(v);
        shi[row * LDB + k] = h;
        slo[row * LDB + k] = __float2half_rn(v - __half2float(h));
    }
}

typedef wmma::fragment<wmma::accumulator, 16, 16, 16, float> AccFrag;

// 3-pass fp16 GEMM body with compile-time trip count (lets ptxas pipeline
// the independent per-tile A loads -> MLP > 1).
template<int NT>
__device__ __forceinline__ void gemm3_fix(const __half* Ahi, const __half* Alo,
                                          unsigned lda, const __half* Bhi,
                                          const __half* Blo, int k0,
                                          AccFrag acc[3]) {
#pragma unroll
    for (int i = 0; i < NT; ++i) {
        const int kt = k0 + i;
        wmma::fragment<wmma::matrix_a, 16, 16, 16, __half, wmma::row_major> ahi, alo;
        wmma::load_matrix_sync(ahi, Ahi + kt * 16, lda);
        wmma::load_matrix_sync(alo, Alo + kt * 16, lda);
#pragma unroll
        for (int gg = 0; gg < 3; gg++) {
            wmma::fragment<wmma::matrix_b, 16, 16, 16, __half, wmma::col_major> bh, bl;
            wmma::load_matrix_sync(bh, Bhi + gg * 16 * LDB + kt * 16, LDB);
            wmma::load_matrix_sync(bl, Blo + gg * 16 * LDB + kt * 16, LDB);
            wmma::mma_sync(acc[gg], ahi, bh, acc[gg]);
            wmma::mma_sync(acc[gg], alo, bh, acc[gg]);
            wmma::mma_sync(acc[gg], ahi, bl, acc[gg]);
        }
    }
}

__device__ __forceinline__ void gemm3(const __half* Ahi, const __half* Alo,
                                      unsigned lda, const __half* Bhi,
                                      const __half* Blo, int k0, int k1,
                                      AccFrag acc[3]) {
    const int nt = k1 - k0;
    if (nt == 5)       gemm3_fix<5>(Ahi, Alo, lda, Bhi, Blo, k0, acc);
    else if (nt == 6)  gemm3_fix<6>(Ahi, Alo, lda, Bhi, Blo, k0, acc);
    else if (nt == 10) gemm3_fix<10>(Ahi, Alo, lda, Bhi, Blo, k0, acc);
    else               gemm3_fix<11>(Ahi, Alo, lda, Bhi, Blo, k0, acc);
}

// 3-phase reduce for bulk (12 warps = 4 rb x 3 ks)
__device__ __forceinline__ void reduce3(float* stage, int tilebase, int ks,
                                        AccFrag acc[3]) {
#pragma unroll
    for (int p = 0; p < 3; p++) {
        if (ks == p) {
#pragma unroll
            for (int gg = 0; gg < 3; gg++) {
                float* tp = stage + (tilebase + gg) * TILE_F;
                if (p > 0) {
                    AccFrag c;
                    wmma::load_matrix_sync(c, tp, SLD, wmma::mem_row_major);
                    for (int i = 0; i < c.num_elements; i++) acc[gg].x[i] += c.x[i];
                }
                wmma::store_matrix_sync(tp, acc[gg], SLD, wmma::mem_row_major);
            }
        }
        __syncthreads();
    }
}

// pairwise reduce for L1 (12 warps = 2 rb x 6 ks -> 18 tiles, 2 phases).
// tile index: ((rb*3 + gg)*3 + pair), pair = ks>>1
__device__ __forceinline__ void reduce_pair(float* stage, int rb, int ks,
                                            AccFrag acc[3]) {
    const int pair = ks >> 1;
    if ((ks & 1) == 0) {
#pragma unroll
        for (int gg = 0; gg < 3; gg++)
            wmma::store_matrix_sync(stage + ((rb * 3 + gg) * 3 + pair) * TILE_F,
                                    acc[gg], SLD, wmma::mem_row_major);
    }
    __syncthreads();
    if (ks & 1) {
#pragma unroll
        for (int gg = 0; gg < 3; gg++) {
            float* tp = stage + ((rb * 3 + gg) * 3 + pair) * TILE_F;
            AccFrag c;
            wmma::load_matrix_sync(c, tp, SLD, wmma::mem_row_major);
            for (int i = 0; i < c.num_elements; i++) acc[gg].x[i] += c.x[i];
            wmma::store_matrix_sync(tp, acc[gg], SLD, wmma::mem_row_major);
        }
    }
    __syncthreads();
}

__device__ __forceinline__ void spin_ge(volatile unsigned int* p, unsigned tgt) {
    while (*p < tgt) { __nanosleep(64); }
}
__device__ __forceinline__ void fence_gpu() {
    asm volatile("fence.acq_rel.gpu;" ::: "memory");
}

// ---------------- bulk: gi0 = x@W_ih0^T + b_ih0 + enc split + counter init ---
extern "C" __global__ void __launch_bounds__(NTHREADS, 1)
gru_bulk(const float* __restrict__ x, const float* __restrict__ enc,
         const float* __restrict__ Wih, const float* __restrict__ bih) {
    extern __shared__ __half smem[];
    __half* shi   = smem;
    __half* slo   = smem + 48 * LDB;
    float*  stage = (float*)(smem + 2 * 48 * LDB);
    __half* abuf  = (__half*)(stage + 12 * TILE_F);

    const int bid = blockIdx.x;
    const int cidx = bid & 31;
    const int tg   = bid >> 5;
    const int tid  = threadIdx.x, wid = tid >> 5, lane = tid & 31;
    const int rb = wid / 3, ks = wid % 3;
    const int k0 = ks * 11, k1 = (ks == 2) ? 32 : k0 + 11;

    {
        size_t i = (size_t)bid * NTHREADS + tid;
        size_t ne = (size_t)2 * BB * KK;
        if (i < ne) {
            int l = (int)(i / (BB * KK));
            int r = (int)(i % (BB * KK));
            float v = enc[i];
            __half hi = __float2half_rn(v);
            g_h_hi[l][1][r] = hi;
            g_h_lo[l][1][r] = __float2half_rn(v - __half2float(hi));
        }
        if (i == 0) {
            g_c0g[0][0] = 0; g_c0g[1][0] = 0;
            g_c1g[0][0] = 0; g_c1g[1][0] = 0;
        }
    }

    load_weights(Wih, shi, slo, cidx);
    __syncthreads();

    __half* myAhi = abuf + wid * 2 * 16 * ABUF_LD;
    __half* myAlo = myAhi + 16 * ABUF_LD;
    const int arow = lane >> 1;
    const int acol = (lane & 1) * 8;

    for (int tt = 0; tt < 32; tt++) {
        int t = tg * 32 + tt;
        AccFrag acc[3];
#pragma unroll
        for (int gg = 0; gg < 3; gg++) wmma::fill_fragment(acc[gg], 0.0f);

        const float* xrow = x + ((size_t)(rb * 16 + arow) * TT + t) * KK;
        for (int kt = k0; kt < k1; ++kt) {
            float4 v0 = *(const float4*)(xrow + kt * 16 + acol);
            float4 v1 = *(const float4*)(xrow + kt * 16 + acol + 4);
            float vv[8] = {v0.x, v0.y, v0.z, v0.w, v1.x, v1.y, v1.z, v1.w};
#pragma unroll
            for (int j = 0; j < 8; j++) {
                __half h = __float2half_rn(vv[j]);
                myAhi[arow * ABUF_LD + acol + j] = h;
                myAlo[arow * ABUF_LD + acol + j] = __float2half_rn(vv[j] - __half2float(h));
            }
            __syncwarp();
            wmma::fragment<wmma::matrix_a, 16, 16, 16, __half, wmma::row_major> ahi, alo;
            wmma::load_matrix_sync(ahi, myAhi, ABUF_LD);
            wmma::load_matrix_sync(alo, myAlo, ABUF_LD);
#pragma unroll
            for (int gg = 0; gg < 3; gg++) {
                wmma::fragment<wmma::matrix_b, 16, 16, 16, __half, wmma::col_major> bh, bl;
                wmma::load_matrix_sync(bh, shi + gg * 16 * LDB + kt * 16, LDB);
                wmma::load_matrix_sync(bl, slo + gg * 16 * LDB + kt * 16, LDB);
                wmma::mma_sync(acc[gg], ahi, bh, acc[gg]);
                wmma::mma_sync(acc[gg], alo, bh, acc[gg]);
                wmma::mma_sync(acc[gg], ahi, bl, acc[gg]);
            }
            __syncwarp();
        }
        reduce3(stage, rb * 3, ks, acc);
        for (int e = tid; e < 64 * 16; e += NTHREADS) {
            int row = e >> 4, c = e & 15, rb2 = row >> 4, rr = row & 15;
            int gc = cidx * 16 + c;
            const float* st = stage + rb2 * 3 * TILE_F;
            float* dst = &g_gi0[((size_t)t * BB + row) * G3];
            dst[gc]        = st[rr * SLD + c]              + bih[gc];
            dst[512 + gc]  = st[TILE_F + rr * SLD + c]     + bih[512 + gc];
            dst[1024 + gc] = st[2 * TILE_F + rr * SLD + c] + bih[1024 + gc];
        }
        __syncthreads();
    }
}

// ---------------- main: L0 = r13; L1 = two-phase (all 12 warps per GEMM) -----
extern "C" __global__ void __launch_bounds__(NTHREADS, 1)
gru_main(const float* __restrict__ Wih, const float* __restrict__ Whh,
         const float* __restrict__ bih, const float* __restrict__ bhh,
         float* __restrict__ out) {
    extern __shared__ __half smem[];
    const int bid = blockIdx.x, tid = threadIdx.x;
    const int wid = tid >> 5, lane = tid & 31;
    const bool L0 = (bid < 64);

    __half *sWih_hi = nullptr, *sWih_lo = nullptr, *sWhh_hi, *sWhh_lo;
    float *stage, *ghsum = nullptr;
    int cidx, grp, b0;

    if (L0) {
        grp = bid >> 5; cidx = bid & 31; b0 = grp * 32;
        sWhh_hi = smem; sWhh_lo = smem + 48 * LDB;
        stage = (float*)(smem + 2 * 48 * LDB);        // 36 tiles
        load_weights(Whh, sWhh_hi, sWhh_lo, cidx);
    } else {
        int r = bid - 64;
        grp = r >> 5; cidx = r & 31; b0 = grp * 32;
        sWih_hi = smem;                sWih_lo = smem + 48 * LDB;
        sWhh_hi = smem + 2 * 48 * LDB; sWhh_lo = smem + 3 * 48 * LDB;
        stage = (float*)(smem + 4 * 48 * LDB);        // 18 tiles
        ghsum = stage + 18 * TILE_F;                  // 384*6 floats
        load_weights(Wih + (size_t)G3 * KK, sWih_hi, sWih_lo, cidx);
        load_weights(Whh + (size_t)G3 * KK, sWhh_hi, sWhh_lo, cidx);
    }
    __syncthreads();

    // both layers: 12 warps = 2 rb x 6 ks, splits {6,6,5,5,5,5}
    const int rb = wid / 6, ks = wid % 6;
    const int k0 = (ks < 2) ? ks * 6 : 12 + (ks - 2) * 5;
    const int k1 = k0 + ((ks < 2) ? 6 : 5);
    const int layer = L0 ? 0 : 1;
    const float* bihL = bih + layer * G3;
    const float* bhhL = bhh + layer * G3;

    // ---- epilogue caches: biases + exact h_prev in registers ----
    float cbiR[2], cbiZ[2], cbiN[2], cbhR[2], cbhZ[2], cbhN[2], hp_reg[2];
    int nelem = 0;
#pragma unroll
    for (int q = 0; q < 2; q++) {
        int e = tid + q * NTHREADS;
        if (e >= 32 * 16) break;
        int row = e >> 4, c = e & 15;
        int gc = cidx * 16 + c;
        int hidx = (b0 + row) * KK + gc;
        cbiR[q] = L0 ? 0.f : bihL[gc];
        cbiZ[q] = L0 ? 0.f : bihL[512 + gc];
        cbiN[q] = L0 ? 0.f : bihL[1024 + gc];
        cbhR[q] = bhhL[gc];
        cbhZ[q] = bhhL[512 + gc];
        cbhN[q] = bhhL[1024 + gc];
        hp_reg[q] = __half2float(g_h_hi[layer][1][hidx]) +
                    __half2float(g_h_lo[layer][1][hidx]);
        nelem++;
    }

    for (int t = 0; t < TT; t++) {
        if (L0) {
            // ---- gi0 prefetch: immutable, overlaps wait + GEMM ----
            float pgi[6];
#pragma unroll
            for (int q = 0; q < 2; q++) {
                int e = tid + q * NTHREADS;
                if (e >= 32 * 16) break;
                int row = e >> 4, c = e & 15;
                const float* gi = &g_gi0[((size_t)t * BB + b0 + row) * G3] + cidx * 16 + c;
                pgi[q * 3 + 0] = gi[0];
                pgi[q * 3 + 1] = gi[512];
                pgi[q * 3 + 2] = gi[1024];
            }

            if (lane == 0) {
                spin_ge(&g_c0g[grp][0], (unsigned)(32 * t));
                if (t >= 1) spin_ge(&g_c1g[grp][0], (unsigned)(32 * (t - 1)));
                fence_gpu();
            }
            __syncwarp();

            int pv = (t + 1) & 1;
            const __half* Ahi = &g_h_hi[0][pv][b0 * KK] + rb * 16 * KK;
            const __half* Alo = &g_h_lo[0][pv][b0 * KK] + rb * 16 * KK;

            AccFrag acc[3];
#pragma unroll
            for (int gg = 0; gg < 3; gg++) wmma::fill_fragment(acc[gg], 0.0f);
            gemm3(Ahi, Alo, KK, sWhh_hi, sWhh_lo, k0, k1, acc);
#pragma unroll
            for (int gg = 0; gg < 3; gg++)
                wmma::store_matrix_sync(stage + (wid * 3 + gg) * TILE_F, acc[gg],
                                        SLD, wmma::mem_row_major);
            __syncthreads();

#pragma unroll
            for (int q = 0; q < 2; q++) {
                if (q >= nelem) break;
                int e = tid + q * NTHREADS;
                int row = e >> 4, c = e & 15, rb2 = row >> 4, rr = row & 15;
                int gc = cidx * 16 + c;
                float ghR = 0.f, ghZ = 0.f, ghN = 0.f;
                const int off = rr * SLD + c;
#pragma unroll
                for (int s = 0; s < 6; s++) {
                    const float* tp = stage + ((rb2 * 6 + s) * 3) * TILE_F + off;
                    ghR += tp[0];
                    ghZ += tp[TILE_F];
                    ghN += tp[2 * TILE_F];
                }
                float r = 1.0f / (1.0f + expf(-(pgi[q * 3 + 0] + ghR + cbhR[q])));
                float z = 1.0f / (1.0f + expf(-(pgi[q * 3 + 1] + ghZ + cbhZ[q])));
                float n = tanhf(pgi[q * 3 + 2] + r * (ghN + cbhN[q]));

                int hidx = (b0 + row) * KK + gc;
                float hn = (1.0f - z) * n + z * hp_reg[q];
                hp_reg[q] = hn;
                int pc = t & 1;
                __half hh = __float2half_rn(hn);
                g_h_hi[0][pc][hidx] = hh;
                g_h_lo[0][pc][hidx] = __float2half_rn(hn - __half2float(hh));
                if (t == TT - 1)
                    out[(size_t)BB * TT * KK + hidx] = hn;
            }
            __syncthreads();
            if (tid == 0) { fence_gpu(); atomicAdd(&g_c0g[grp][0], 1u); }
        } else {
            // ================= L1: two-phase =================
            // Phase gh: needs h1(t-1) only — all 12 warps, 6-way ksplit
            if (lane == 0) {
                spin_ge(&g_c1g[grp][0], (unsigned)(32 * t));
                fence_gpu();
            }
            __syncwarp();
            {
                int pv = (t + 1) & 1;
                const __half* Ahi = &g_h_hi[1][pv][b0 * KK] + rb * 16 * KK;
                const __half* Alo = &g_h_lo[1][pv][b0 * KK] + rb * 16 * KK;
                AccFrag acc[3];
#pragma unroll
                for (int gg = 0; gg < 3; gg++) wmma::fill_fragment(acc[gg], 0.0f);
                gemm3(Ahi, Alo, KK, sWhh_hi, sWhh_lo, k0, k1, acc);
                reduce_pair(stage, rb, ks, acc);
            }
            // extract gh sums to scratch (stage gets reused by gi)
#pragma unroll
            for (int q = 0; q < 2; q++) {
                if (q >= nelem) break;
                int e = tid + q * NTHREADS;
                int row = e >> 4, c = e & 15, rb2 = row >> 4, rr = row & 15;
                const int off = rr * SLD + c;
#pragma unroll
                for (int gg = 0; gg < 3; gg++) {
                    float s = 0.f;
#pragma unroll
                    for (int p = 0; p < 3; p++)
                        s += stage[((rb2 * 3 + gg) * 3 + p) * TILE_F + off];
                    ghsum[tid * 6 + q * 3 + gg] = s;
                }
            }
            __syncthreads();

            // Phase gi: needs h0(t) — all 12 warps, 6-way ksplit
            if (lane == 0) {
                spin_ge(&g_c0g[grp][0], (unsigned)(32 * (t + 1)));
                fence_gpu();
            }
            __syncwarp();
            {
                int p0 = t & 1;
                const __half* Ahi = &g_h_hi[0][p0][b0 * KK] + rb * 16 * KK;
                const __half* Alo = &g_h_lo[0][p0][b0 * KK] + rb * 16 * KK;
                AccFrag acc[3];
#pragma unroll
                for (int gg = 0; gg < 3; gg++) wmma::fill_fragment(acc[gg], 0.0f);
                gemm3(Ahi, Alo, KK, sWih_hi, sWih_lo, k0, k1, acc);
                reduce_pair(stage, rb, ks, acc);
            }

#pragma unroll
            for (int q = 0; q < 2; q++) {
                if (q >= nelem) break;
                int e = tid + q * NTHREADS;
                int row = e >> 4, c = e & 15, rb2 = row >> 4, rr = row & 15;
                int gc = cidx * 16 + c;
                const int off = rr * SLD + c;
                float gi3[3];
#pragma unroll
                for (int gg = 0; gg < 3; gg++) {
                    float s = 0.f;
#pragma unroll
                    for (int p = 0; p < 3; p++)
                        s += stage[((rb2 * 3 + gg) * 3 + p) * TILE_F + off];
                    gi3[gg] = s;
                }
                float ghR = ghsum[tid * 6 + q * 3 + 0];
                float ghZ = ghsum[tid * 6 + q * 3 + 1];
                float ghN = ghsum[tid * 6 + q * 3 + 2];
                float r = 1.0f / (1.0f + expf(-(gi3[0] + cbiR[q] + ghR + cbhR[q])));
                float z = 1.0f / (1.0f + expf(-(gi3[1] + cbiZ[q] + ghZ + cbhZ[q])));
                float n = tanhf(gi3[2] + cbiN[q] + r * (ghN + cbhN[q]));

                int hidx = (b0 + row) * KK + gc;
                float hn = (1.0f - z) * n + z * hp_reg[q];
                hp_reg[q] = hn;
                int pc = t & 1;
                __half hh = __float2half_rn(hn);
                g_h_hi[1][pc][hidx] = hh;
                g_h_lo[1][pc][hidx] = __float2half_rn(hn - __half2float(hh));
                out[((size_t)(b0 + row) * TT + t) * KK + gc] = hn;
                if (t == TT - 1)
                    out[(size_t)BB * TT * KK + (size_t)BB * KK + hidx] = hn;
            }
            __syncthreads();
            if (tid == 0) { fence_gpu(); atomicAdd(&g_c1g[grp][0], 1u); }
        }
    }
}

extern "C" void kernel_launch(void* const* d_in, const int* in_sizes, int n_in,
                              void* d_out, int out_size) {
    const float* x   = (const float*)d_in[0];
    const float* enc = (const float*)d_in[1];
    const float* Wih = (const float*)d_in[2];
    const float* Whh = (const float*)d_in[3];
    const float* bih = (const float*)d_in[4];
    const float* bhh = (const float*)d_in[5];
    float* out = (float*)d_out;
    (void)in_sizes; (void)n_in; (void)out_size;

    // L1: 199,680 (weights) + 23,040 (18 tiles) + 9,216 (ghsum) = 231,936 B
    size_t smem_main = (size_t)4 * 48 * LDB * 2 + (size_t)18 * TILE_F * 4
                     + (size_t)NTHREADS * 6 * 4;
    size_t smem_bulk = (size_t)2 * 48 * LDB * 2 + (size_t)12 * TILE_F * 4
                     + (size_t)12 * 2 * 16 * ABUF_LD * 2;
    cudaFuncSetAttribute(gru_main, cudaFuncAttributeMaxDynamicSharedMemorySize,
                         (int)smem_main);
    cudaFuncSetAttribute(gru_bulk, cudaFuncAttributeMaxDynamicSharedMemorySize,
                         (int)smem_bulk);

    gru_bulk<<<512, NTHREADS, smem_bulk>>>(x, enc, Wih, bih);
    gru_main<<<128, NTHREADS, smem_main>>>(Wih, Whh, bih, bhh, out);
}

// round 15
// speedup vs baseline: 1.2281x; 1.2281x over previous
#include <cuda_runtime.h>
#include <cuda_fp16.h>
#include <mma.h>

using namespace nvcuda;

#define BB   64
#define TT   512
#define KK   512
#define G3   1536
#define LDB  520
#define NTHREADS 384
#define SLD  20
#define TILE_F (16*SLD)

__device__ __half g_x_hi[(size_t)BB * TT * KK];
__device__ __half g_x_lo[(size_t)BB * TT * KK];
__device__ __half g_h_hi[2][2][BB * KK];
__device__ __half g_h_lo[2][2][BB * KK];
__device__ float  g_gi0[(size_t)TT * BB * G3];
__device__ __align__(128) unsigned int g_c0g[2][32];
__device__ __align__(128) unsigned int g_c1g[2][32];

// ---------------- prepass: split x + enc to fp16 hi/lo, init counters --------
__global__ void gru_prepass(const float* __restrict__ x,
                            const float* __restrict__ enc) {
    size_t i = (size_t)blockIdx.x * blockDim.x + threadIdx.x;
    size_t stride = (size_t)gridDim.x * blockDim.x;
    size_t n = (size_t)BB * TT * KK;
    for (size_t idx = i; idx < n; idx += stride) {
        float v = x[idx];
        __half hi = __float2half_rn(v);
        g_x_hi[idx] = hi;
        g_x_lo[idx] = __float2half_rn(v - __half2float(hi));
    }
    size_t ne = (size_t)2 * BB * KK;
    for (size_t idx = i; idx < ne; idx += stride) {
        int l = (int)(idx / (BB * KK));
        int r = (int)(idx % (BB * KK));
        float v = enc[idx];
        __half hi = __float2half_rn(v);
        g_h_hi[l][1][r] = hi;
        g_h_lo[l][1][r] = __float2half_rn(v - __half2float(hi));
    }
    if (i == 0) {
        g_c0g[0][0] = 0; g_c0g[1][0] = 0;
        g_c1g[0][0] = 0; g_c1g[1][0] = 0;
    }
}

__device__ __forceinline__ void load_weights(const float* __restrict__ W,
                                             __half* shi, __half* slo, int cidx) {
    for (int idx = threadIdx.x; idx < 48 * KK; idx += NTHREADS) {
        int row = idx >> 9, k = idx & 511;
        int grow = (row >> 4) * 512 + cidx * 16 + (row & 15);
        float v = W[(size_t)grow * KK + k];
        __half h = __float2half_rn(v);
        shi[row * LDB + k] = h;
        slo[row * LDB + k] = __float2half_rn(v - __half2float(h));
    }
}

typedef wmma::fragment<wmma::accumulator, 16, 16, 16, float> AccFrag;

// 3-pass fp16 GEMM with compile-time trip count (pipelined A loads, MLP>1)
template<int NT>
__device__ __forceinline__ void gemm3_fix(const __half* Ahi, const __half* Alo,
                                          unsigned lda, const __half* Bhi,
                                          const __half* Blo, int k0,
                                          AccFrag acc[3]) {
#pragma unroll
    for (int i = 0; i < NT; ++i) {
        const int kt = k0 + i;
        wmma::fragment<wmma::matrix_a, 16, 16, 16, __half, wmma::row_major> ahi, alo;
        wmma::load_matrix_sync(ahi, Ahi + kt * 16, lda);
        wmma::load_matrix_sync(alo, Alo + kt * 16, lda);
#pragma unroll
        for (int gg = 0; gg < 3; gg++) {
            wmma::fragment<wmma::matrix_b, 16, 16, 16, __half, wmma::col_major> bh, bl;
            wmma::load_matrix_sync(bh, Bhi + gg * 16 * LDB + kt * 16, LDB);
            wmma::load_matrix_sync(bl, Blo + gg * 16 * LDB + kt * 16, LDB);
            wmma::mma_sync(acc[gg], ahi, bh, acc[gg]);
            wmma::mma_sync(acc[gg], alo, bh, acc[gg]);
            wmma::mma_sync(acc[gg], ahi, bl, acc[gg]);
        }
    }
}

__device__ __forceinline__ void gemm3(const __half* Ahi, const __half* Alo,
                                      unsigned lda, const __half* Bhi,
                                      const __half* Blo, int k0, int k1,
                                      AccFrag acc[3]) {
    const int nt = k1 - k0;
    if (nt == 5)       gemm3_fix<5>(Ahi, Alo, lda, Bhi, Blo, k0, acc);
    else if (nt == 6)  gemm3_fix<6>(Ahi, Alo, lda, Bhi, Blo, k0, acc);
    else if (nt == 10) gemm3_fix<10>(Ahi, Alo, lda, Bhi, Blo, k0, acc);
    else               gemm3_fix<11>(Ahi, Alo, lda, Bhi, Blo, k0, acc);
}

// 3-phase reduce (12 warps = 4 rb x 3 ks)
__device__ __forceinline__ void reduce3(float* stage, int tilebase, int ks,
                                        AccFrag acc[3]) {
#pragma unroll
    for (int p = 0; p < 3; p++) {
        if (ks == p) {
#pragma unroll
            for (int gg = 0; gg < 3; gg++) {
                float* tp = stage + (tilebase + gg) * TILE_F;
                if (p > 0) {
                    AccFrag c;
                    wmma::load_matrix_sync(c, tp, SLD, wmma::mem_row_major);
                    for (int i = 0; i < c.num_elements; i++) acc[gg].x[i] += c.x[i];
                }
                wmma::store_matrix_sync(tp, acc[gg], SLD, wmma::mem_row_major);
            }
        }
        __syncthreads();
    }
}

__device__ __forceinline__ void spin_ge(volatile unsigned int* p, unsigned tgt) {
    while (*p < tgt) { __nanosleep(64); }
}
__device__ __forceinline__ void fence_gpu() {
    asm volatile("fence.acq_rel.gpu;" ::: "memory");
}

// ---------------- bulk: gi0 = x@W_ih0^T + b_ih0 (templated GEMM, no staging) -
extern "C" __global__ void __launch_bounds__(NTHREADS, 1)
gru_bulk(const float* __restrict__ Wih, const float* __restrict__ bih) {
    extern __shared__ __half smem[];
    __half* shi   = smem;
    __half* slo   = smem + 48 * LDB;
    float*  stage = (float*)(smem + 2 * 48 * LDB);

    const int bid = blockIdx.x;
    const int cidx = bid & 31;
    const int tg   = bid >> 5;
    const int tid  = threadIdx.x, wid = tid >> 5;
    const int rb = wid / 3, ks = wid % 3;
    const int k0 = ks * 11, k1 = (ks == 2) ? 32 : k0 + 11;

    load_weights(Wih, shi, slo, cidx);
    __syncthreads();

    for (int tt = 0; tt < 32; tt++) {
        int t = tg * 32 + tt;
        const __half* Ahi = g_x_hi + ((size_t)(rb * 16) * TT + t) * KK;
        const __half* Alo = g_x_lo + ((size_t)(rb * 16) * TT + t) * KK;
        AccFrag acc[3];
#pragma unroll
        for (int gg = 0; gg < 3; gg++) wmma::fill_fragment(acc[gg], 0.0f);
        gemm3(Ahi, Alo, (unsigned)(TT * KK), shi, slo, k0, k1, acc);
        reduce3(stage, rb * 3, ks, acc);
        for (int e = tid; e < 64 * 16; e += NTHREADS) {
            int row = e >> 4, c = e & 15, rb2 = row >> 4, rr = row & 15;
            int gc = cidx * 16 + c;
            const float* st = stage + rb2 * 3 * TILE_F;
            float* dst = &g_gi0[((size_t)t * BB + row) * G3];
            dst[gc]        = st[rr * SLD + c]              + bih[gc];
            dst[512 + gc]  = st[TILE_F + rr * SLD + c]     + bih[512 + gc];
            dst[1024 + gc] = st[2 * TILE_F + rr * SLD + c] + bih[1024 + gc];
        }
        __syncthreads();
    }
}

// ---------------- main: 64 L0 (6-way ksplit) + 64 L1 (r13 verbatim) ----------
extern "C" __global__ void __launch_bounds__(NTHREADS, 1)
gru_main(const float* __restrict__ Wih, const float* __restrict__ Whh,
         const float* __restrict__ bih, const float* __restrict__ bhh,
         float* __restrict__ out) {
    extern __shared__ __half smem[];
    const int bid = blockIdx.x, tid = threadIdx.x;
    const int wid = tid >> 5, lane = tid & 31;
    const bool L0 = (bid < 64);

    __half *sWih_hi = nullptr, *sWih_lo = nullptr, *sWhh_hi, *sWhh_lo;
    float* stage;
    int cidx, grp, b0;

    if (L0) {
        grp = bid >> 5; cidx = bid & 31; b0 = grp * 32;
        sWhh_hi = smem; sWhh_lo = smem + 48 * LDB;
        stage = (float*)(smem + 2 * 48 * LDB);        // 36 tiles
        load_weights(Whh, sWhh_hi, sWhh_lo, cidx);
    } else {
        int r = bid - 64;
        grp = r >> 5; cidx = r & 31; b0 = grp * 32;
        sWih_hi = smem;                sWih_lo = smem + 48 * LDB;
        sWhh_hi = smem + 2 * 48 * LDB; sWhh_lo = smem + 3 * 48 * LDB;
        stage = (float*)(smem + 4 * 48 * LDB);        // 12 tiles
        load_weights(Wih + (size_t)G3 * KK, sWih_hi, sWih_lo, cidx);
        load_weights(Whh + (size_t)G3 * KK, sWhh_hi, sWhh_lo, cidx);
    }
    __syncthreads();

    int srcid, rb, ks, k0, k1;
    if (L0) {
        srcid = 1; rb = wid / 6; ks = wid % 6;
        k0 = (ks < 2) ? ks * 6 : 12 + (ks - 2) * 5;
        k1 = k0 + ((ks < 2) ? 6 : 5);
    } else {
        srcid = wid / 6; rb = (wid % 6) / 3; ks = wid % 3;
        k0 = ks * 11; k1 = (ks == 2) ? 32 : k0 + 11;
    }
    const int tilebase = L0 ? 0 : ((srcid * 2 + rb) * 3);
    const int layer = L0 ? 0 : 1;
    const float* bihL = bih + layer * G3;
    const float* bhhL = bhh + layer * G3;

    float cbiR[2], cbiZ[2], cbiN[2], cbhR[2], cbhZ[2], cbhN[2], hp_reg[2];
    int nelem = 0;
#pragma unroll
    for (int q = 0; q < 2; q++) {
        int e = tid + q * NTHREADS;
        if (e >= 32 * 16) break;
        int row = e >> 4, c = e & 15;
        int gc = cidx * 16 + c;
        int hidx = (b0 + row) * KK + gc;
        cbiR[q] = L0 ? 0.f : bihL[gc];
        cbiZ[q] = L0 ? 0.f : bihL[512 + gc];
        cbiN[q] = L0 ? 0.f : bihL[1024 + gc];
        cbhR[q] = bhhL[gc];
        cbhZ[q] = bhhL[512 + gc];
        cbhN[q] = bhhL[1024 + gc];
        hp_reg[q] = __half2float(g_h_hi[layer][1][hidx]) +
                    __half2float(g_h_lo[layer][1][hidx]);
        nelem++;
    }

    for (int t = 0; t < TT; t++) {
        float pgi[6];
        if (L0) {
#pragma unroll
            for (int q = 0; q < 2; q++) {
                int e = tid + q * NTHREADS;
                if (e >= 32 * 16) break;
                int row = e >> 4, c = e & 15;
                const float* gi = &g_gi0[((size_t)t * BB + b0 + row) * G3] + cidx * 16 + c;
                pgi[q * 3 + 0] = gi[0];
                pgi[q * 3 + 1] = gi[512];
                pgi[q * 3 + 2] = gi[1024];
            }
        }

        if (lane == 0) {
            if (L0) {
                spin_ge(&g_c0g[grp][0], (unsigned)(32 * t));
                if (t >= 1) spin_ge(&g_c1g[grp][0], (unsigned)(32 * (t - 1)));
            } else if (srcid == 0) {
                spin_ge(&g_c0g[grp][0], (unsigned)(32 * (t + 1)));  // need h0(t)
            } else {
                spin_ge(&g_c1g[grp][0], (unsigned)(32 * t));        // need h1(t-1)
            }
            fence_gpu();
        }
        __syncwarp();

        const __half *Ahi, *Alo;
        if (L0) {
            int pv = (t + 1) & 1;
            Ahi = &g_h_hi[0][pv][b0 * KK] + rb * 16 * KK;
            Alo = &g_h_lo[0][pv][b0 * KK] + rb * 16 * KK;
        } else if (srcid == 0) {
            int p = t & 1;
            Ahi = &g_h_hi[0][p][b0 * KK] + rb * 16 * KK;
            Alo = &g_h_lo[0][p][b0 * KK] + rb * 16 * KK;
        } else {
            int pv = (t + 1) & 1;
            Ahi = &g_h_hi[1][pv][b0 * KK] + rb * 16 * KK;
            Alo = &g_h_lo[1][pv][b0 * KK] + rb * 16 * KK;
        }
        const __half* Bh = (srcid == 0) ? sWih_hi : sWhh_hi;
        const __half* Bl = (srcid == 0) ? sWih_lo : sWhh_lo;

        AccFrag acc[3];
#pragma unroll
        for (int gg = 0; gg < 3; gg++) wmma::fill_fragment(acc[gg], 0.0f);
        gemm3(Ahi, Alo, KK, Bh, Bl, k0, k1, acc);

        if (L0) {
#pragma unroll
            for (int gg = 0; gg < 3; gg++)
                wmma::store_matrix_sync(stage + (wid * 3 + gg) * TILE_F, acc[gg],
                                        SLD, wmma::mem_row_major);
            __syncthreads();
        } else {
            reduce3(stage, tilebase, ks, acc);
        }

#pragma unroll
        for (int q = 0; q < 2; q++) {
            if (q >= nelem) break;
            int e = tid + q * NTHREADS;
            int row = e >> 4, c = e & 15, rb2 = row >> 4, rr = row & 15;
            int gc = cidx * 16 + c;
            float giR, giZ, giN, ghR, ghZ, ghN;
            if (L0) {
                giR = pgi[q * 3 + 0]; giZ = pgi[q * 3 + 1]; giN = pgi[q * 3 + 2];
                ghR = 0.f; ghZ = 0.f; ghN = 0.f;
                const int off = rr * SLD + c;
#pragma unroll
                for (int s = 0; s < 6; s++) {
                    const float* tp = stage + ((rb2 * 6 + s) * 3) * TILE_F + off;
                    ghR += tp[0];
                    ghZ += tp[TILE_F];
                    ghN += tp[2 * TILE_F];
                }
            } else {
                const float* sg = stage + rb2 * 3 * TILE_F;
                const float* sh = stage + (2 + rb2) * 3 * TILE_F;
                giR = sg[rr * SLD + c]              + cbiR[q];
                giZ = sg[TILE_F + rr * SLD + c]     + cbiZ[q];
                giN = sg[2 * TILE_F + rr * SLD + c] + cbiN[q];
                ghR = sh[rr * SLD + c];
                ghZ = sh[TILE_F + rr * SLD + c];
                ghN = sh[2 * TILE_F + rr * SLD + c];
            }
            float r = 1.0f / (1.0f + expf(-(giR + ghR + cbhR[q])));
            float z = 1.0f / (1.0f + expf(-(giZ + ghZ + cbhZ[q])));
            float n = tanhf(giN + r * (ghN + cbhN[q]));

            int hidx = (b0 + row) * KK + gc;
            float hn = (1.0f - z) * n + z * hp_reg[q];
            hp_reg[q] = hn;

            int pc = t & 1;
            __half hh = __float2half_rn(hn);
            g_h_hi[layer][pc][hidx] = hh;
            g_h_lo[layer][pc][hidx] = __float2half_rn(hn - __half2float(hh));

            if (!L0)
                out[((size_t)(b0 + row) * TT + t) * KK + gc] = hn;
            if (t == TT - 1)
                out[(size_t)BB * TT * KK + (size_t)layer * BB * KK + hidx] = hn;
        }
        __syncthreads();
        if (tid == 0) {
            fence_gpu();
            if (L0) atomicAdd(&g_c0g[grp][0], 1u);
            else    atomicAdd(&g_c1g[grp][0], 1u);
        }
    }
}

extern "C" void kernel_launch(void* const* d_in, const int* in_sizes, int n_in,
                              void* d_out, int out_size) {
    const float* x   = (const float*)d_in[0];
    const float* enc = (const float*)d_in[1];
    const float* Wih = (const float*)d_in[2];
    const float* Whh = (const float*)d_in[3];
    const float* bih = (const float*)d_in[4];
    const float* bhh = (const float*)d_in[5];
    float* out = (float*)d_out;
    (void)in_sizes; (void)n_in; (void)out_size;

    size_t smem_main = (size_t)4 * 48 * LDB * 2 + (size_t)12 * TILE_F * 4; // 215040
    size_t smem_bulk = (size_t)2 * 48 * LDB * 2 + (size_t)12 * TILE_F * 4; // 115200
    cudaFuncSetAttribute(gru_main, cudaFuncAttributeMaxDynamicSharedMemorySize,
                         (int)smem_main);
    cudaFuncSetAttribute(gru_bulk, cudaFuncAttributeMaxDynamicSharedMemorySize,
                         (int)smem_bulk);

    gru_prepass<<<2048, 256>>>(x, enc);
    gru_bulk<<<512, NTHREADS, smem_bulk>>>(Wih, bih);
    gru_main<<<128, NTHREADS, smem_main>>>(Wih, Whh, bih, bhh, out);
}

// round 16
// speedup vs baseline: 1.2302x; 1.0017x over previous
#include <cuda_runtime.h>
#include <cuda_fp16.h>
#include <mma.h>

using namespace nvcuda;

#define BB   64
#define TT   512
#define KK   512
#define G3   1536
#define LDB  520
#define NTHREADS 384
#define SLD  20
#define TILE_F (16*SLD)
#define ABUF_LD 24

__device__ __half g_h_hi[2][2][BB * KK];
__device__ __half g_h_lo[2][2][BB * KK];
__device__ float  g_gi0[(size_t)TT * BB * G3];
__device__ __align__(128) unsigned int g_c0g[2][32];
__device__ __align__(128) unsigned int g_c1g[2][32];

#define BAR_SYNC(id, n) asm volatile("bar.sync %0, %1;" :: "r"(id), "r"(n) : "memory")

__device__ __forceinline__ void load_weights(const float* __restrict__ W,
                                             __half* shi, __half* slo, int cidx) {
    for (int idx = threadIdx.x; idx < 48 * KK; idx += NTHREADS) {
        int row = idx >> 9, k = idx & 511;
        int grow = (row >> 4) * 512 + cidx * 16 + (row & 15);
        float v = W[(size_t)grow * KK + k];
        __half h = __float2half_rn(v);
        shi[row * LDB + k] = h;
        slo[row * LDB + k] = __float2half_rn(v - __half2float(h));
    }
}

typedef wmma::fragment<wmma::accumulator, 16, 16, 16, float> AccFrag;

// 3-pass fp16 GEMM with compile-time trip count (pipelined A loads, MLP>1)
template<int NT>
__device__ __forceinline__ void gemm3_fix(const __half* Ahi, const __half* Alo,
                                          unsigned lda, const __half* Bhi,
                                          const __half* Blo, int k0,
                                          AccFrag acc[3]) {
#pragma unroll
    for (int i = 0; i < NT; ++i) {
        const int kt = k0 + i;
        wmma::fragment<wmma::matrix_a, 16, 16, 16, __half, wmma::row_major> ahi, alo;
        wmma::load_matrix_sync(ahi, Ahi + kt * 16, lda);
        wmma::load_matrix_sync(alo, Alo + kt * 16, lda);
#pragma unroll
        for (int gg = 0; gg < 3; gg++) {
            wmma::fragment<wmma::matrix_b, 16, 16, 16, __half, wmma::col_major> bh, bl;
            wmma::load_matrix_sync(bh, Bhi + gg * 16 * LDB + kt * 16, LDB);
            wmma::load_matrix_sync(bl, Blo + gg * 16 * LDB + kt * 16, LDB);
            wmma::mma_sync(acc[gg], ahi, bh, acc[gg]);
            wmma::mma_sync(acc[gg], alo, bh, acc[gg]);
            wmma::mma_sync(acc[gg], ahi, bl, acc[gg]);
        }
    }
}

__device__ __forceinline__ void gemm3(const __half* Ahi, const __half* Alo,
                                      unsigned lda, const __half* Bhi,
                                      const __half* Blo, int k0, int k1,
                                      AccFrag acc[3]) {
    const int nt = k1 - k0;
    if (nt == 5)       gemm3_fix<5>(Ahi, Alo, lda, Bhi, Blo, k0, acc);
    else if (nt == 6)  gemm3_fix<6>(Ahi, Alo, lda, Bhi, Blo, k0, acc);
    else if (nt == 8)  gemm3_fix<8>(Ahi, Alo, lda, Bhi, Blo, k0, acc);
    else if (nt == 10) gemm3_fix<10>(Ahi, Alo, lda, Bhi, Blo, k0, acc);
    else if (nt == 11) gemm3_fix<11>(Ahi, Alo, lda, Bhi, Blo, k0, acc);
    else               gemm3_fix<16>(Ahi, Alo, lda, Bhi, Blo, k0, acc);
}

// 3-phase reduce (bulk: 12 warps = 4 rb x 3 ks)
__device__ __forceinline__ void reduce3(float* stage, int tilebase, int ks,
                                        AccFrag acc[3]) {
#pragma unroll
    for (int p = 0; p < 3; p++) {
        if (ks == p) {
#pragma unroll
            for (int gg = 0; gg < 3; gg++) {
                float* tp = stage + (tilebase + gg) * TILE_F;
                if (p > 0) {
                    AccFrag c;
                    wmma::load_matrix_sync(c, tp, SLD, wmma::mem_row_major);
                    for (int i = 0; i < c.num_elements; i++) acc[gg].x[i] += c.x[i];
                }
                wmma::store_matrix_sync(tp, acc[gg], SLD, wmma::mem_row_major);
            }
        }
        __syncthreads();
    }
}

__device__ __forceinline__ void spin_ge(volatile unsigned int* p, unsigned tgt) {
    while (*p < tgt) { __nanosleep(64); }
}
__device__ __forceinline__ void fence_gpu() {
    asm volatile("fence.acq_rel.gpu;" ::: "memory");
}

// ---------------- bulk (r13 verbatim): gi0 + enc split + counter init --------
extern "C" __global__ void __launch_bounds__(NTHREADS, 1)
gru_bulk(const float* __restrict__ x, const float* __restrict__ enc,
         const float* __restrict__ Wih, const float* __restrict__ bih) {
    extern __shared__ __half smem[];
    __half* shi   = smem;
    __half* slo   = smem + 48 * LDB;
    float*  stage = (float*)(smem + 2 * 48 * LDB);
    __half* abuf  = (__half*)(stage + 12 * TILE_F);

    const int bid = blockIdx.x;
    const int cidx = bid & 31;
    const int tg   = bid >> 5;
    const int tid  = threadIdx.x, wid = tid >> 5, lane = tid & 31;
    const int rb = wid / 3, ks = wid % 3;
    const int k0 = ks * 11, k1 = (ks == 2) ? 32 : k0 + 11;

    {
        size_t i = (size_t)bid * NTHREADS + tid;
        size_t ne = (size_t)2 * BB * KK;
        if (i < ne) {
            int l = (int)(i / (BB * KK));
            int r = (int)(i % (BB * KK));
            float v = enc[i];
            __half hi = __float2half_rn(v);
            g_h_hi[l][1][r] = hi;
            g_h_lo[l][1][r] = __float2half_rn(v - __half2float(hi));
        }
        if (i == 0) {
            g_c0g[0][0] = 0; g_c0g[1][0] = 0;
            g_c1g[0][0] = 0; g_c1g[1][0] = 0;
        }
    }

    load_weights(Wih, shi, slo, cidx);
    __syncthreads();

    __half* myAhi = abuf + wid * 2 * 16 * ABUF_LD;
    __half* myAlo = myAhi + 16 * ABUF_LD;
    const int arow = lane >> 1;
    const int acol = (lane & 1) * 8;

    for (int tt = 0; tt < 32; tt++) {
        int t = tg * 32 + tt;
        AccFrag acc[3];
#pragma unroll
        for (int gg = 0; gg < 3; gg++) wmma::fill_fragment(acc[gg], 0.0f);

        const float* xrow = x + ((size_t)(rb * 16 + arow) * TT + t) * KK;
        for (int kt = k0; kt < k1; ++kt) {
            float4 v0 = *(const float4*)(xrow + kt * 16 + acol);
            float4 v1 = *(const float4*)(xrow + kt * 16 + acol + 4);
            float vv[8] = {v0.x, v0.y, v0.z, v0.w, v1.x, v1.y, v1.z, v1.w};
#pragma unroll
            for (int j = 0; j < 8; j++) {
                __half h = __float2half_rn(vv[j]);
                myAhi[arow * ABUF_LD + acol + j] = h;
                myAlo[arow * ABUF_LD + acol + j] = __float2half_rn(vv[j] - __half2float(h));
            }
            __syncwarp();
            wmma::fragment<wmma::matrix_a, 16, 16, 16, __half, wmma::row_major> ahi, alo;
            wmma::load_matrix_sync(ahi, myAhi, ABUF_LD);
            wmma::load_matrix_sync(alo, myAlo, ABUF_LD);
#pragma unroll
            for (int gg = 0; gg < 3; gg++) {
                wmma::fragment<wmma::matrix_b, 16, 16, 16, __half, wmma::col_major> bh, bl;
                wmma::load_matrix_sync(bh, shi + gg * 16 * LDB + kt * 16, LDB);
                wmma::load_matrix_sync(bl, slo + gg * 16 * LDB + kt * 16, LDB);
                wmma::mma_sync(acc[gg], ahi, bh, acc[gg]);
                wmma::mma_sync(acc[gg], alo, bh, acc[gg]);
                wmma::mma_sync(acc[gg], ahi, bl, acc[gg]);
            }
            __syncwarp();
        }
        reduce3(stage, rb * 3, ks, acc);
        for (int e = tid; e < 64 * 16; e += NTHREADS) {
            int row = e >> 4, c = e & 15, rb2 = row >> 4, rr = row & 15;
            int gc = cidx * 16 + c;
            const float* st = stage + rb2 * 3 * TILE_F;
            float* dst = &g_gi0[((size_t)t * BB + row) * G3];
            dst[gc]        = st[rr * SLD + c]              + bih[gc];
            dst[512 + gc]  = st[TILE_F + rr * SLD + c]     + bih[512 + gc];
            dst[1024 + gc] = st[2 * TILE_F + rr * SLD + c] + bih[1024 + gc];
        }
        __syncthreads();
    }
}

// ---------------- main: L0 = r13; L1 = asymmetric 8gi/4gh --------------------
extern "C" __global__ void __launch_bounds__(NTHREADS, 1)
gru_main(const float* __restrict__ Wih, const float* __restrict__ Whh,
         const float* __restrict__ bih, const float* __restrict__ bhh,
         float* __restrict__ out) {
    extern __shared__ __half smem[];
    const int bid = blockIdx.x, tid = threadIdx.x;
    const int wid = tid >> 5, lane = tid & 31;
    const bool L0 = (bid < 64);

    __half *sWih_hi = nullptr, *sWih_lo = nullptr, *sWhh_hi, *sWhh_lo;
    float* stage;
    int cidx, grp, b0;

    if (L0) {
        grp = bid >> 5; cidx = bid & 31; b0 = grp * 32;
        sWhh_hi = smem; sWhh_lo = smem + 48 * LDB;
        stage = (float*)(smem + 2 * 48 * LDB);        // 36 tiles
        load_weights(Whh, sWhh_hi, sWhh_lo, cidx);
    } else {
        int r = bid - 64;
        grp = r >> 5; cidx = r & 31; b0 = grp * 32;
        sWih_hi = smem;                sWih_lo = smem + 48 * LDB;
        sWhh_hi = smem + 2 * 48 * LDB; sWhh_lo = smem + 3 * 48 * LDB;
        stage = (float*)(smem + 4 * 48 * LDB);        // 18 tiles (12 gi + 6 gh)
        load_weights(Wih + (size_t)G3 * KK, sWih_hi, sWih_lo, cidx);
        load_weights(Whh + (size_t)G3 * KK, sWhh_hi, sWhh_lo, cidx);
    }
    __syncthreads();

    // warp roles
    int rb, ks, k0, k1;
    bool is_gi = false;
    if (L0) {
        rb = wid / 6; ks = wid % 6;
        k0 = (ks < 2) ? ks * 6 : 12 + (ks - 2) * 5;   // {6,6,5,5,5,5}
        k1 = k0 + ((ks < 2) ? 6 : 5);
    } else {
        is_gi = (wid < 8);
        if (is_gi) { rb = wid >> 2; ks = wid & 3; k0 = ks * 8;  k1 = k0 + 8;  }
        else { int w = wid - 8; rb = w >> 1; ks = w & 1; k0 = ks * 16; k1 = k0 + 16; }
    }
    const int layer = L0 ? 0 : 1;
    const float* bihL = bih + layer * G3;
    const float* bhhL = bhh + layer * G3;

    // epilogue caches: biases + exact h_prev in registers
    float cbiR[2], cbiZ[2], cbiN[2], cbhR[2], cbhZ[2], cbhN[2], hp_reg[2];
    int nelem = 0;
#pragma unroll
    for (int q = 0; q < 2; q++) {
        int e = tid + q * NTHREADS;
        if (e >= 32 * 16) break;
        int row = e >> 4, c = e & 15;
        int gc = cidx * 16 + c;
        int hidx = (b0 + row) * KK + gc;
        cbiR[q] = L0 ? 0.f : bihL[gc];
        cbiZ[q] = L0 ? 0.f : bihL[512 + gc];
        cbiN[q] = L0 ? 0.f : bihL[1024 + gc];
        cbhR[q] = bhhL[gc];
        cbhZ[q] = bhhL[512 + gc];
        cbhN[q] = bhhL[1024 + gc];
        hp_reg[q] = __half2float(g_h_hi[layer][1][hidx]) +
                    __half2float(g_h_lo[layer][1][hidx]);
        nelem++;
    }

    for (int t = 0; t < TT; t++) {
        if (L0) {
            // ---- L0 (r13 verbatim) ----
            float pgi[6];
#pragma unroll
            for (int q = 0; q < 2; q++) {
                int e = tid + q * NTHREADS;
                if (e >= 32 * 16) break;
                int row = e >> 4, c = e & 15;
                const float* gi = &g_gi0[((size_t)t * BB + b0 + row) * G3] + cidx * 16 + c;
                pgi[q * 3 + 0] = gi[0];
                pgi[q * 3 + 1] = gi[512];
                pgi[q * 3 + 2] = gi[1024];
            }
            if (lane == 0) {
                spin_ge(&g_c0g[grp][0], (unsigned)(32 * t));
                if (t >= 1) spin_ge(&g_c1g[grp][0], (unsigned)(32 * (t - 1)));
                fence_gpu();
            }
            __syncwarp();

            int pv = (t + 1) & 1;
            const __half* Ahi = &g_h_hi[0][pv][b0 * KK] + rb * 16 * KK;
            const __half* Alo = &g_h_lo[0][pv][b0 * KK] + rb * 16 * KK;
            AccFrag acc[3];
#pragma unroll
            for (int gg = 0; gg < 3; gg++) wmma::fill_fragment(acc[gg], 0.0f);
            gemm3(Ahi, Alo, KK, sWhh_hi, sWhh_lo, k0, k1, acc);
#pragma unroll
            for (int gg = 0; gg < 3; gg++)
                wmma::store_matrix_sync(stage + (wid * 3 + gg) * TILE_F, acc[gg],
                                        SLD, wmma::mem_row_major);
            __syncthreads();

#pragma unroll
            for (int q = 0; q < 2; q++) {
                if (q >= nelem) break;
                int e = tid + q * NTHREADS;
                int row = e >> 4, c = e & 15, rb2 = row >> 4, rr = row & 15;
                int gc = cidx * 16 + c;
                float ghR = 0.f, ghZ = 0.f, ghN = 0.f;
                const int off = rr * SLD + c;
#pragma unroll
                for (int s = 0; s < 6; s++) {
                    const float* tp = stage + ((rb2 * 6 + s) * 3) * TILE_F + off;
                    ghR += tp[0];
                    ghZ += tp[TILE_F];
                    ghN += tp[2 * TILE_F];
                }
                float r = 1.0f / (1.0f + expf(-(pgi[q * 3 + 0] + ghR + cbhR[q])));
                float z = 1.0f / (1.0f + expf(-(pgi[q * 3 + 1] + ghZ + cbhZ[q])));
                float n = tanhf(pgi[q * 3 + 2] + r * (ghN + cbhN[q]));
                int hidx = (b0 + row) * KK + gc;
                float hn = (1.0f - z) * n + z * hp_reg[q];
                hp_reg[q] = hn;
                int pc = t & 1;
                __half hh = __float2half_rn(hn);
                g_h_hi[0][pc][hidx] = hh;
                g_h_lo[0][pc][hidx] = __float2half_rn(hn - __half2float(hh));
                if (t == TT - 1)
                    out[(size_t)BB * TT * KK + hidx] = hn;
            }
            __syncthreads();
            if (tid == 0) { fence_gpu(); atomicAdd(&g_c0g[grp][0], 1u); }
        } else {
            // ---- L1: 8 gi warps (8 serial tiles) + 4 gh warps (16, slack) ----
            if (lane == 0) {
                if (is_gi) spin_ge(&g_c0g[grp][0], (unsigned)(32 * (t + 1)));
                else       spin_ge(&g_c1g[grp][0], (unsigned)(32 * t));
                fence_gpu();
            }
            __syncwarp();

            const __half *Ahi, *Alo;
            if (is_gi) {
                int p = t & 1;
                Ahi = &g_h_hi[0][p][b0 * KK] + rb * 16 * KK;
                Alo = &g_h_lo[0][p][b0 * KK] + rb * 16 * KK;
            } else {
                int pv = (t + 1) & 1;
                Ahi = &g_h_hi[1][pv][b0 * KK] + rb * 16 * KK;
                Alo = &g_h_lo[1][pv][b0 * KK] + rb * 16 * KK;
            }
            const __half* Bh = is_gi ? sWih_hi : sWhh_hi;
            const __half* Bl = is_gi ? sWih_lo : sWhh_lo;

            AccFrag acc[3];
#pragma unroll
            for (int gg = 0; gg < 3; gg++) wmma::fill_fragment(acc[gg], 0.0f);
            gemm3(Ahi, Alo, KK, Bh, Bl, k0, k1, acc);

            if (is_gi) {
                // pairwise reduce among 8 gi warps (named barrier 1, 256 thr)
                const int pair = ks >> 1;
                if ((ks & 1) == 0) {
#pragma unroll
                    for (int gg = 0; gg < 3; gg++)
                        wmma::store_matrix_sync(
                            stage + (rb * 6 + gg * 2 + pair) * TILE_F, acc[gg],
                            SLD, wmma::mem_row_major);
                }
                BAR_SYNC(1, 256);
                if (ks & 1) {
#pragma unroll
                    for (int gg = 0; gg < 3; gg++) {
                        float* tp = stage + (rb * 6 + gg * 2 + pair) * TILE_F;
                        AccFrag c;
                        wmma::load_matrix_sync(c, tp, SLD, wmma::mem_row_major);
                        for (int i = 0; i < c.num_elements; i++) acc[gg].x[i] += c.x[i];
                        wmma::store_matrix_sync(tp, acc[gg], SLD, wmma::mem_row_major);
                    }
                }
            } else {
                // pairwise reduce among 4 gh warps (named barrier 2, 128 thr)
                if (ks == 0) {
#pragma unroll
                    for (int gg = 0; gg < 3; gg++)
                        wmma::store_matrix_sync(
                            stage + (12 + rb * 3 + gg) * TILE_F, acc[gg],
                            SLD, wmma::mem_row_major);
                }
                BAR_SYNC(2, 128);
                if (ks == 1) {
#pragma unroll
                    for (int gg = 0; gg < 3; gg++) {
                        float* tp = stage + (12 + rb * 3 + gg) * TILE_F;
                        AccFrag c;
                        wmma::load_matrix_sync(c, tp, SLD, wmma::mem_row_major);
                        for (int i = 0; i < c.num_elements; i++) acc[gg].x[i] += c.x[i];
                        wmma::store_matrix_sync(tp, acc[gg], SLD, wmma::mem_row_major);
                    }
                }
            }
            __syncthreads();

            // epilogue
#pragma unroll
            for (int q = 0; q < 2; q++) {
                if (q >= nelem) break;
                int e = tid + q * NTHREADS;
                int row = e >> 4, c = e & 15, rb2 = row >> 4, rr = row & 15;
                int gc = cidx * 16 + c;
                const int off = rr * SLD + c;
                float giR = stage[(rb2 * 6 + 0) * TILE_F + off]
                          + stage[(rb2 * 6 + 1) * TILE_F + off] + cbiR[q];
                float giZ = stage[(rb2 * 6 + 2) * TILE_F + off]
                          + stage[(rb2 * 6 + 3) * TILE_F + off] + cbiZ[q];
                float giN = stage[(rb2 * 6 + 4) * TILE_F + off]
                          + stage[(rb2 * 6 + 5) * TILE_F + off] + cbiN[q];
                float ghR = stage[(12 + rb2 * 3 + 0) * TILE_F + off];
                float ghZ = stage[(12 + rb2 * 3 + 1) * TILE_F + off];
                float ghN = stage[(12 + rb2 * 3 + 2) * TILE_F + off];

                float r = 1.0f / (1.0f + expf(-(giR + ghR + cbhR[q])));
                float z = 1.0f / (1.0f + expf(-(giZ + ghZ + cbhZ[q])));
                float n = tanhf(giN + r * (ghN + cbhN[q]));
                int hidx = (b0 + row) * KK + gc;
                float hn = (1.0f - z) * n + z * hp_reg[q];
                hp_reg[q] = hn;
                int pc = t & 1;
                __half hh = __float2half_rn(hn);
                g_h_hi[1][pc][hidx] = hh;
                g_h_lo[1][pc][hidx] = __float2half_rn(hn - __half2float(hh));
            }
            __syncthreads();
            if (tid == 0) { fence_gpu(); atomicAdd(&g_c1g[grp][0], 1u); }

            // out writes AFTER publish (pure sink, off critical loop)
#pragma unroll
            for (int q = 0; q < 2; q++) {
                if (q >= nelem) break;
                int e = tid + q * NTHREADS;
                int row = e >> 4, c = e & 15;
                int gc = cidx * 16 + c;
                out[((size_t)(b0 + row) * TT + t) * KK + gc] = hp_reg[q];
                if (t == TT - 1)
                    out[(size_t)BB * TT * KK + (size_t)BB * KK + (b0 + row) * KK + gc] = hp_reg[q];
            }
        }
    }
}

extern "C" void kernel_launch(void* const* d_in, const int* in_sizes, int n_in,
                              void* d_out, int out_size) {
    const float* x   = (const float*)d_in[0];
    const float* enc = (const float*)d_in[1];
    const float* Wih = (const float*)d_in[2];
    const float* Whh = (const float*)d_in[3];
    const float* bih = (const float*)d_in[4];
    const float* bhh = (const float*)d_in[5];
    float* out = (float*)d_out;
    (void)in_sizes; (void)n_in; (void)out_size;

    size_t smem_main = (size_t)4 * 48 * LDB * 2 + (size_t)36 * TILE_F * 4; // 245,?  L0 needs 36 tiles
    // L0 stage sits after only 2 weight matrices: usage = 99,840 + 46,080 = 145,920
    // L1 usage = 199,680 + 18*1280 = 222,720  -> allocate max(222720, ...)
    smem_main = 222720;
    size_t smem_bulk = (size_t)2 * 48 * LDB * 2 + (size_t)12 * TILE_F * 4
                     + (size_t)12 * 2 * 16 * ABUF_LD * 2;
    cudaFuncSetAttribute(gru_main, cudaFuncAttributeMaxDynamicSharedMemorySize,
                         (int)smem_main);
    cudaFuncSetAttribute(gru_bulk, cudaFuncAttributeMaxDynamicSharedMemorySize,
                         (int)smem_bulk);

    gru_bulk<<<512, NTHREADS, smem_bulk>>>(x, enc, Wih, bih);
    gru_main<<<128, NTHREADS, smem_main>>>(Wih, Whh, bih, bhh, out);
}